// round 15
// baseline (speedup 1.0000x reference)
#include <cuda_runtime.h>
#include <cuda_bf16.h>
#include <cstdint>

#define TT 512
#define CC 64
#define NB 1024   // B*T
#define NCHUNK_BLKS 1280

// scratch (allocation-free rule: __device__ globals)
__device__ float g_kp[NB * CC];
__device__ float g_qp[NB * CC];           // qp + b1 folded
__device__ float g_v [NB * CC];
__device__ float g_logits[NB * TT];
__device__ uint4 g_Wfrag[1024];           // B fragments: [kt][nt2][lane]
__device__ int g_cnt[NB];                 // per-row chunk counters (self-reset)

// ---------------- kernel 1: projections (1 token/block) + W1p fragments ----------------
__global__ __launch_bounds__(192) void prep_kernel(
    const float* __restrict__ x, const float* __restrict__ pos,
    const float* __restrict__ W1, const float* __restrict__ b1,
    const float* __restrict__ Wv, const float* __restrict__ bv)
{
    const int tid = threadIdx.x;
    const int bid = blockIdx.x;

    if (bid >= NB) {
        // build B fragments exactly as ldmatrix.x4 would deliver them (proven R11/R12).
        if (tid < 128) {
            int idx  = (bid - NB) * 128 + tid;    // 0..1023
            int lane = idx & 31;
            int nt2  = (idx >> 5) & 3;
            int kt   = idx >> 7;
            int n0 = nt2 * 16 + (lane >> 2);
            int k0 = kt * 16 + 2 * (lane & 3);
            const float* Wp = W1 + 128 * 64;      // W1p base, [k][n]
            float a00 = Wp[(k0    ) * 64 + n0],     a01 = Wp[(k0 + 1) * 64 + n0];
            float a10 = Wp[(k0 + 8) * 64 + n0],     a11 = Wp[(k0 + 9) * 64 + n0];
            float a20 = Wp[(k0    ) * 64 + n0 + 8], a21 = Wp[(k0 + 1) * 64 + n0 + 8];
            float a30 = Wp[(k0 + 8) * 64 + n0 + 8], a31 = Wp[(k0 + 9) * 64 + n0 + 8];
            __nv_bfloat162 h0 = __floats2bfloat162_rn(a00, a01);
            __nv_bfloat162 h1 = __floats2bfloat162_rn(a10, a11);
            __nv_bfloat162 h2 = __floats2bfloat162_rn(a20, a21);
            __nv_bfloat162 h3 = __floats2bfloat162_rn(a30, a31);
            uint4 u;
            u.x = *(uint32_t*)&h0;
            u.y = *(uint32_t*)&h1;
            u.z = *(uint32_t*)&h2;
            u.w = *(uint32_t*)&h3;
            g_Wfrag[idx] = u;
        }
        return;
    }

    __shared__ float xs[64], x1s[64];
    const int bi = bid;                   // token index (b*T + t)
    if (tid < 64) {
        float xv = x[bi * 64 + tid];
        xs [tid] = xv;
        x1s[tid] = xv + pos[(bi & (TT - 1)) * 64 + tid];
    }
    __syncthreads();

    const int m = tid >> 6;               // 0 kp, 1 qp, 2 v
    const int c = tid & 63;

    const float* Wp = (m == 0) ? W1 : (m == 1) ? (W1 + 4096) : Wv;
    const float* in = (m == 2) ? xs : x1s;

    float a = 0.f;
#pragma unroll 16
    for (int k = 0; k < 64; k++)
        a = fmaf(in[k], Wp[k * 64 + c], a);

    if (m == 0)      g_kp[bi * 64 + c] = a;
    else if (m == 1) g_qp[bi * 64 + c] = a + b1[c];
    else             g_v [bi * 64 + c] = a + bv[c];
}

// ---------------- kernel 2: R12 champion attn (unchanged) ----------------
__global__ __launch_bounds__(256, 4) void attn_kernel(
    const float* __restrict__ pdist,
    const float* __restrict__ W2,
    const float* __restrict__ b2,
    float* __restrict__ out)
{
    __shared__ __nv_bfloat16 As[128 * 136];   // 34816 B, padded stride 136
    __shared__ float qp_s[64];
    __shared__ float W2_s[64];                // pre-scaled by 0.125

    // winner aliases over As (dead after MMA phase)
    float* ls    = (float*)As;                // 512 f
    float* red   = (float*)As + 512;          // 16*64 f
    float* rbuf  = (float*)As + 512 + 1024;   // 8 f
    int*   sflag = (int*)((float*)As + 512 + 1024 + 8);

    const int tid = threadIdx.x;

    // decode (b, i, ch)
    int z = blockIdx.x;
    int b = 0;
    if (z >= NCHUNK_BLKS) { b = 1; z -= NCHUNK_BLKS; }
    int ch, i;
    if (z < 512)       { ch = 0; i = z; }
    else if (z < 896)  { ch = 1; i = 128 + (z - 512); }
    else if (z < 1152) { ch = 2; i = 256 + (z - 896); }
    else               { ch = 3; i = 384 + (z - 1152); }
    const int bi    = b * TT + i;
    const int jbase = ch << 7;
    const int imax  = i - jbase;
    const int nch   = (i >> 7) + 1;

    const int lane = tid & 31;
    const int w    = tid >> 5;
    const int g    = lane >> 2;
    const int tc   = lane & 3;
    const int wrow = w * 16;
    const bool active = (wrow <= imax);

    // ---- pdist loads first: DRAM latency up front, per-warp rows ----
    if (active) {
        const int rmaxi = imax - wrow;
        const float4* src = (const float4*)(pdist + ((size_t)bi * TT + jbase) * 128);
#pragma unroll
        for (int r = 0; r < 16; r++) {
            if (r <= rmaxi) {
                int jloc = wrow + r;
                float4 vv = src[jloc * 32 + lane];
                __nv_bfloat162 lo = __floats2bfloat162_rn(vv.x, vv.y);
                __nv_bfloat162 hi = __floats2bfloat162_rn(vv.z, vv.w);
                uint2 u;
                u.x = *(uint32_t*)&lo;
                u.y = *(uint32_t*)&hi;
                *(uint2*)((char*)As + jloc * 272 + lane * 8) = u;
            }
        }
    }
    if (tid < 64) {
        qp_s[tid] = g_qp[bi * 64 + tid];
        W2_s[tid] = W2[tid] * 0.125f;
    }
    __syncthreads();

    if (active) {
        uint32_t As_u = (uint32_t)__cvta_generic_to_shared(As);
        uint32_t a_base = As_u + (uint32_t)((wrow + (lane & 7) + ((lane >> 3) & 1) * 8) * 272
                                            + (lane >> 4) * 16);

        float acc[32];
#pragma unroll
        for (int zz = 0; zz < 32; zz++) acc[zz] = 0.f;

        const uint4* wf = g_Wfrag + lane;

#pragma unroll
        for (int kt = 0; kt < 8; kt++) {
            uint32_t a0, a1, a2, a3;
            asm volatile("ldmatrix.sync.aligned.m8n8.x4.shared.b16 {%0,%1,%2,%3}, [%4];"
                         : "=r"(a0), "=r"(a1), "=r"(a2), "=r"(a3)
                         : "r"(a_base + kt * 32));
#pragma unroll
            for (int nt2 = 0; nt2 < 4; nt2++) {
                uint4 bb = __ldg(wf + (kt * 4 + nt2) * 32);
                asm volatile(
                    "mma.sync.aligned.m16n8k16.row.col.f32.bf16.bf16.f32 "
                    "{%0,%1,%2,%3}, {%4,%5,%6,%7}, {%8,%9}, {%0,%1,%2,%3};"
                    : "+f"(acc[nt2 * 8 + 0]), "+f"(acc[nt2 * 8 + 1]),
                      "+f"(acc[nt2 * 8 + 2]), "+f"(acc[nt2 * 8 + 3])
                    : "r"(a0), "r"(a1), "r"(a2), "r"(a3), "r"(bb.x), "r"(bb.y));
                asm volatile(
                    "mma.sync.aligned.m16n8k16.row.col.f32.bf16.bf16.f32 "
                    "{%0,%1,%2,%3}, {%4,%5,%6,%7}, {%8,%9}, {%0,%1,%2,%3};"
                    : "+f"(acc[nt2 * 8 + 4]), "+f"(acc[nt2 * 8 + 5]),
                      "+f"(acc[nt2 * 8 + 6]), "+f"(acc[nt2 * 8 + 7])
                    : "r"(a0), "r"(a1), "r"(a2), "r"(a3), "r"(bb.z), "r"(bb.w));
            }
        }

        // fused epilogue: +qp_s+kp, gelu (ex2+rcp), dot with pre-scaled W2
        const int j0 = jbase + wrow + g;
        const int j1 = j0 + 8;
        const float* kp0 = g_kp + ((size_t)(b * TT + j0)) * 64;
        const float* kp1 = kp0 + 8 * 64;
        float pa = 0.f, pb = 0.f;
#pragma unroll
        for (int nt = 0; nt < 8; nt++) {
            int c = nt * 8 + 2 * tc;
            float2 k0 = *(const float2*)(kp0 + c);
            float2 k1 = *(const float2*)(kp1 + c);
            float2 qv = *(const float2*)(qp_s + c);
            float w20 = W2_s[c], w21 = W2_s[c + 1];
            float hh, h2, e, d, rc;
            hh = acc[nt * 4 + 0] + qv.x + k0.x;
            h2 = hh * hh;
            asm("ex2.approx.f32 %0, %1;" : "=f"(e)
                : "f"(hh * fmaf(-0.10294324f, h2, -2.3022087f)));
            d = e + 1.f;
            asm("rcp.approx.f32 %0, %1;" : "=f"(rc) : "f"(d));
            pa = fmaf(w20, hh * rc, pa);
            hh = acc[nt * 4 + 1] + qv.y + k0.y;
            h2 = hh * hh;
            asm("ex2.approx.f32 %0, %1;" : "=f"(e)
                : "f"(hh * fmaf(-0.10294324f, h2, -2.3022087f)));
            d = e + 1.f;
            asm("rcp.approx.f32 %0, %1;" : "=f"(rc) : "f"(d));
            pa = fmaf(w21, hh * rc, pa);
            hh = acc[nt * 4 + 2] + qv.x + k1.x;
            h2 = hh * hh;
            asm("ex2.approx.f32 %0, %1;" : "=f"(e)
                : "f"(hh * fmaf(-0.10294324f, h2, -2.3022087f)));
            d = e + 1.f;
            asm("rcp.approx.f32 %0, %1;" : "=f"(rc) : "f"(d));
            pb = fmaf(w20, hh * rc, pb);
            hh = acc[nt * 4 + 3] + qv.y + k1.y;
            h2 = hh * hh;
            asm("ex2.approx.f32 %0, %1;" : "=f"(e)
                : "f"(hh * fmaf(-0.10294324f, h2, -2.3022087f)));
            d = e + 1.f;
            asm("rcp.approx.f32 %0, %1;" : "=f"(rc) : "f"(d));
            pb = fmaf(w21, hh * rc, pb);
        }
        pa += __shfl_xor_sync(0xffffffffu, pa, 1);
        pa += __shfl_xor_sync(0xffffffffu, pa, 2);
        pb += __shfl_xor_sync(0xffffffffu, pb, 1);
        pb += __shfl_xor_sync(0xffffffffu, pb, 2);
        if (tc == 0) {
            g_logits[bi * TT + j0] = pa;   // already ×0.125
            g_logits[bi * TT + j1] = pb;
        }
    }

    // ---- winner election ----
    __syncthreads();
    if (tid == 0) {
        __threadfence();
        int old = atomicAdd(&g_cnt[bi], 1);
        if (old == nch - 1) {
            *sflag = 1;
            g_cnt[bi] = 0;   // self-reset for graph replay
        } else {
            *sflag = 0;
        }
    }
    __syncthreads();
    if (!*sflag) return;
    __threadfence();  // acquire

    // ---- winner: softmax (logits pre-scaled; add b2*0.125) ----
    const float b2v = b2[0] * 0.125f;
    float lmax = -1e30f;
    for (int j = tid; j <= i; j += 256) {
        float l = __ldcg(&g_logits[bi * TT + j]) + b2v;
        ls[j] = l;
        lmax = fmaxf(lmax, l);
    }
#pragma unroll
    for (int o = 16; o; o >>= 1) lmax = fmaxf(lmax, __shfl_xor_sync(0xffffffffu, lmax, o));
    if (lane == 0) rbuf[w] = lmax;
    __syncthreads();
    float gmax = rbuf[0];
#pragma unroll
    for (int zz = 1; zz < 8; zz++) gmax = fmaxf(gmax, rbuf[zz]);
    __syncthreads();

    float lsum = 0.f;
    for (int j = tid; j <= i; j += 256) {
        float p = __expf(ls[j] - gmax);
        ls[j] = p;
        lsum += p;
    }
#pragma unroll
    for (int o = 16; o; o >>= 1) lsum += __shfl_xor_sync(0xffffffffu, lsum, o);
    if (lane == 0) rbuf[w] = lsum;
    __syncthreads();
    float tot = rbuf[0];
#pragma unroll
    for (int zz = 1; zz < 8; zz++) tot += rbuf[zz];
    const float inv = 1.f / tot;
    __syncthreads();

    // ---- winner: wei@v, vectorized float4 ----
    {
        const int hg = tid & 15;
        const int js = tid >> 4;
        const float4* v4 = (const float4*)(g_v + (size_t)b * TT * 64);
        float4 a4 = make_float4(0.f, 0.f, 0.f, 0.f);
#pragma unroll 4
        for (int j = js; j <= i; j += 16) {
            float wei = ls[j];
            float4 vv = v4[j * 16 + hg];
            a4.x = fmaf(wei, vv.x, a4.x);
            a4.y = fmaf(wei, vv.y, a4.y);
            a4.z = fmaf(wei, vv.z, a4.z);
            a4.w = fmaf(wei, vv.w, a4.w);
        }
        *(float4*)(red + js * 64 + hg * 4) = a4;
        __syncthreads();
        if (tid < 64) {
            float r = 0.f;
#pragma unroll
            for (int s = 0; s < 16; s++) r += red[s * 64 + tid];
            out[bi * 64 + tid] = r * inv;
        }
    }
}

// ---------------- launcher ----------------
extern "C" void kernel_launch(void* const* d_in, const int* in_sizes, int n_in,
                              void* d_out, int out_size)
{
    const float* x     = (const float*)d_in[0];
    const float* pos   = (const float*)d_in[1];
    const float* pdist = (const float*)d_in[2];
    const float* W1    = (const float*)d_in[3];
    const float* b1    = (const float*)d_in[4];
    const float* W2    = (const float*)d_in[5];
    const float* b2    = (const float*)d_in[6];
    const float* Wv    = (const float*)d_in[7];
    const float* bv    = (const float*)d_in[8];
    float* out = (float*)d_out;

    prep_kernel<<<NB + 8, 192>>>(x, pos, W1, b1, Wv, bv);
    attn_kernel<<<2 * NCHUNK_BLKS, 256>>>(pdist, W2, b2, out);
}

// round 16
// speedup vs baseline: 1.3508x; 1.3508x over previous
#include <cuda_runtime.h>
#include <cuda_bf16.h>
#include <cstdint>

#define TT 512
#define CC 64
#define NB 1024   // B*T
#define NCHUNK_BLKS 1280

// scratch (allocation-free rule: __device__ globals)
__device__ float g_kp[NB * CC];
__device__ float g_qp[NB * CC];           // qp + b1 folded
__device__ float g_v [NB * CC];
__device__ float g_logits[NB * TT];
__device__ uint4 g_Wfrag[1024];           // B fragments: [kt][nt2][lane]
__device__ int g_cnt[NB];                 // per-row chunk counters (self-reset)

// ---------------- kernel 1: projections + W1p fragment precompute ----------------
__global__ __launch_bounds__(384) void prep_kernel(
    const float* __restrict__ x, const float* __restrict__ pos,
    const float* __restrict__ W1, const float* __restrict__ b1,
    const float* __restrict__ Wv, const float* __restrict__ bv)
{
    const int tid = threadIdx.x;
    const int bid = blockIdx.x;

    if (bid >= 512) {
        // build B fragments exactly as ldmatrix.x4 would deliver them.
        if (tid < 128) {
            int idx  = (bid - 512) * 128 + tid;   // 0..1023
            int lane = idx & 31;
            int nt2  = (idx >> 5) & 3;
            int kt   = idx >> 7;
            int n0 = nt2 * 16 + (lane >> 2);
            int k0 = kt * 16 + 2 * (lane & 3);
            const float* Wp = W1 + 128 * 64;      // W1p base, [k][n]
            float a00 = Wp[(k0    ) * 64 + n0],     a01 = Wp[(k0 + 1) * 64 + n0];
            float a10 = Wp[(k0 + 8) * 64 + n0],     a11 = Wp[(k0 + 9) * 64 + n0];
            float a20 = Wp[(k0    ) * 64 + n0 + 8], a21 = Wp[(k0 + 1) * 64 + n0 + 8];
            float a30 = Wp[(k0 + 8) * 64 + n0 + 8], a31 = Wp[(k0 + 9) * 64 + n0 + 8];
            __nv_bfloat162 h0 = __floats2bfloat162_rn(a00, a01);
            __nv_bfloat162 h1 = __floats2bfloat162_rn(a10, a11);
            __nv_bfloat162 h2 = __floats2bfloat162_rn(a20, a21);
            __nv_bfloat162 h3 = __floats2bfloat162_rn(a30, a31);
            uint4 u;
            u.x = *(uint32_t*)&h0;
            u.y = *(uint32_t*)&h1;
            u.z = *(uint32_t*)&h2;
            u.w = *(uint32_t*)&h3;
            g_Wfrag[idx] = u;
        }
        return;
    }

    __shared__ float xs[128], x1s[128];
    const int t0 = bid * 2;
    if (tid < 128) {
        int tl = tid >> 6, c = tid & 63;
        float xv = x[(t0 + tl) * 64 + c];
        xs [tid] = xv;
        x1s[tid] = xv + pos[(((t0 + tl) & (TT - 1)) * 64) + c];
    }
    __syncthreads();

    const int tok = tid / 192;
    const int m   = (tid % 192) >> 6;
    const int c   = tid & 63;
    const int bi  = t0 + tok;

    const float* Wp = (m == 0) ? W1 : (m == 1) ? (W1 + 4096) : Wv;
    const float* in = (m == 2) ? (xs + tok * 64) : (x1s + tok * 64);

    float a = 0.f;
#pragma unroll 8
    for (int k = 0; k < 64; k++)
        a = fmaf(in[k], Wp[k * 64 + c], a);

    if (m == 0)      g_kp[bi * 64 + c] = a;
    else if (m == 1) g_qp[bi * 64 + c] = a + b1[c];
    else             g_v [bi * 64 + c] = a + bv[c];
}

// ---------------- kernel 2: smem-A + gmem-B-frag mma.sync, 64 regs, no Wt ----------------
__global__ __launch_bounds__(256, 4) void attn_kernel(
    const float* __restrict__ pdist,
    const float* __restrict__ W2,
    const float* __restrict__ b2,
    float* __restrict__ out)
{
    __shared__ __nv_bfloat16 As[128 * 136];   // 34816 B, padded stride 136
    __shared__ float qp_s[64];
    __shared__ float W2_s[64];                // pre-scaled by 0.125

    // winner aliases over As (dead after MMA phase)
    float* ls    = (float*)As;                // 512 f
    float* red   = (float*)As + 512;          // 16*64 f
    float* rbuf  = (float*)As + 512 + 1024;   // 8 f
    int*   sflag = (int*)((float*)As + 512 + 1024 + 8);

    const int tid = threadIdx.x;

    // decode (b, i, ch)
    int z = blockIdx.x;
    int b = 0;
    if (z >= NCHUNK_BLKS) { b = 1; z -= NCHUNK_BLKS; }
    int ch, i;
    if (z < 512)       { ch = 0; i = z; }
    else if (z < 896)  { ch = 1; i = 128 + (z - 512); }
    else if (z < 1152) { ch = 2; i = 256 + (z - 896); }
    else               { ch = 3; i = 384 + (z - 1152); }
    const int bi    = b * TT + i;
    const int jbase = ch << 7;
    const int imax  = i - jbase;
    const int nch   = (i >> 7) + 1;

    const int lane = tid & 31;
    const int w    = tid >> 5;
    const int g    = lane >> 2;
    const int tc   = lane & 3;
    const int wrow = w * 16;
    const bool active = (wrow <= imax);

    // ---- pdist loads first: DRAM latency up front, per-warp rows ----
    if (active) {
        const int rmaxi = imax - wrow;
        const float4* src = (const float4*)(pdist + ((size_t)bi * TT + jbase) * 128);
#pragma unroll
        for (int r = 0; r < 16; r++) {
            if (r <= rmaxi) {
                int jloc = wrow + r;
                float4 vv = src[jloc * 32 + lane];
                __nv_bfloat162 lo = __floats2bfloat162_rn(vv.x, vv.y);
                __nv_bfloat162 hi = __floats2bfloat162_rn(vv.z, vv.w);
                uint2 u;
                u.x = *(uint32_t*)&lo;
                u.y = *(uint32_t*)&hi;
                *(uint2*)((char*)As + jloc * 272 + lane * 8) = u;
            }
        }
    }
    // qp/W2 staging overlaps the outstanding DRAM loads
    if (tid < 64) {
        qp_s[tid] = g_qp[bi * 64 + tid];
        W2_s[tid] = W2[tid] * 0.125f;
    }
    __syncthreads();   // qp_s ready; own-warp As ordered by barrier too

    if (active) {
        uint32_t As_u = (uint32_t)__cvta_generic_to_shared(As);
        uint32_t a_base = As_u + (uint32_t)((wrow + (lane & 7) + ((lane >> 3) & 1) * 8) * 272
                                            + (lane >> 4) * 16);

        float acc[32];
#pragma unroll
        for (int zz = 0; zz < 32; zz++) acc[zz] = 0.f;

        const uint4* wf = g_Wfrag + lane;

#pragma unroll
        for (int kt = 0; kt < 8; kt++) {
            uint32_t a0, a1, a2, a3;
            asm volatile("ldmatrix.sync.aligned.m8n8.x4.shared.b16 {%0,%1,%2,%3}, [%4];"
                         : "=r"(a0), "=r"(a1), "=r"(a2), "=r"(a3)
                         : "r"(a_base + kt * 32));
#pragma unroll
            for (int nt2 = 0; nt2 < 4; nt2++) {
                uint4 bb = __ldg(wf + (kt * 4 + nt2) * 32);
                asm volatile(
                    "mma.sync.aligned.m16n8k16.row.col.f32.bf16.bf16.f32 "
                    "{%0,%1,%2,%3}, {%4,%5,%6,%7}, {%8,%9}, {%0,%1,%2,%3};"
                    : "+f"(acc[nt2 * 8 + 0]), "+f"(acc[nt2 * 8 + 1]),
                      "+f"(acc[nt2 * 8 + 2]), "+f"(acc[nt2 * 8 + 3])
                    : "r"(a0), "r"(a1), "r"(a2), "r"(a3), "r"(bb.x), "r"(bb.y));
                asm volatile(
                    "mma.sync.aligned.m16n8k16.row.col.f32.bf16.bf16.f32 "
                    "{%0,%1,%2,%3}, {%4,%5,%6,%7}, {%8,%9}, {%0,%1,%2,%3};"
                    : "+f"(acc[nt2 * 8 + 4]), "+f"(acc[nt2 * 8 + 5]),
                      "+f"(acc[nt2 * 8 + 6]), "+f"(acc[nt2 * 8 + 7])
                    : "r"(a0), "r"(a1), "r"(a2), "r"(a3), "r"(bb.z), "r"(bb.w));
            }
        }

        // fused epilogue: +qp_s+kp, gelu (ex2+rcp), dot with pre-scaled W2
        const int j0 = jbase + wrow + g;
        const int j1 = j0 + 8;
        const float* kp0 = g_kp + ((size_t)(b * TT + j0)) * 64;
        const float* kp1 = kp0 + 8 * 64;
        float pa = 0.f, pb = 0.f;
#pragma unroll
        for (int nt = 0; nt < 8; nt++) {
            int c = nt * 8 + 2 * tc;
            float2 k0 = *(const float2*)(kp0 + c);
            float2 k1 = *(const float2*)(kp1 + c);
            float2 qv = *(const float2*)(qp_s + c);
            float w20 = W2_s[c], w21 = W2_s[c + 1];
            float hh, h2, e, d, rc;
            hh = acc[nt * 4 + 0] + qv.x + k0.x;
            h2 = hh * hh;
            asm("ex2.approx.f32 %0, %1;" : "=f"(e)
                : "f"(hh * fmaf(-0.10294324f, h2, -2.3022087f)));
            d = e + 1.f;
            asm("rcp.approx.f32 %0, %1;" : "=f"(rc) : "f"(d));
            pa = fmaf(w20, hh * rc, pa);
            hh = acc[nt * 4 + 1] + qv.y + k0.y;
            h2 = hh * hh;
            asm("ex2.approx.f32 %0, %1;" : "=f"(e)
                : "f"(hh * fmaf(-0.10294324f, h2, -2.3022087f)));
            d = e + 1.f;
            asm("rcp.approx.f32 %0, %1;" : "=f"(rc) : "f"(d));
            pa = fmaf(w21, hh * rc, pa);
            hh = acc[nt * 4 + 2] + qv.x + k1.x;
            h2 = hh * hh;
            asm("ex2.approx.f32 %0, %1;" : "=f"(e)
                : "f"(hh * fmaf(-0.10294324f, h2, -2.3022087f)));
            d = e + 1.f;
            asm("rcp.approx.f32 %0, %1;" : "=f"(rc) : "f"(d));
            pb = fmaf(w20, hh * rc, pb);
            hh = acc[nt * 4 + 3] + qv.y + k1.y;
            h2 = hh * hh;
            asm("ex2.approx.f32 %0, %1;" : "=f"(e)
                : "f"(hh * fmaf(-0.10294324f, h2, -2.3022087f)));
            d = e + 1.f;
            asm("rcp.approx.f32 %0, %1;" : "=f"(rc) : "f"(d));
            pb = fmaf(w21, hh * rc, pb);
        }
        pa += __shfl_xor_sync(0xffffffffu, pa, 1);
        pa += __shfl_xor_sync(0xffffffffu, pa, 2);
        pb += __shfl_xor_sync(0xffffffffu, pb, 1);
        pb += __shfl_xor_sync(0xffffffffu, pb, 2);
        if (tc == 0) {
            g_logits[bi * TT + j0] = pa;   // already ×0.125
            g_logits[bi * TT + j1] = pb;
        }
    }

    // ---- winner election ----
    __syncthreads();
    if (tid == 0) {
        __threadfence();
        int old = atomicAdd(&g_cnt[bi], 1);
        if (old == nch - 1) {
            *sflag = 1;
            g_cnt[bi] = 0;   // self-reset for graph replay
        } else {
            *sflag = 0;
        }
    }
    __syncthreads();
    if (!*sflag) return;
    __threadfence();  // acquire

    // ---- winner: softmax (logits pre-scaled; add b2*0.125) ----
    const float b2v = b2[0] * 0.125f;
    float lmax = -1e30f;
    for (int j = tid; j <= i; j += 256) {
        float l = __ldcg(&g_logits[bi * TT + j]) + b2v;
        ls[j] = l;
        lmax = fmaxf(lmax, l);
    }
#pragma unroll
    for (int o = 16; o; o >>= 1) lmax = fmaxf(lmax, __shfl_xor_sync(0xffffffffu, lmax, o));
    if (lane == 0) rbuf[w] = lmax;
    __syncthreads();
    float gmax = rbuf[0];
#pragma unroll
    for (int zz = 1; zz < 8; zz++) gmax = fmaxf(gmax, rbuf[zz]);
    __syncthreads();

    float lsum = 0.f;
    for (int j = tid; j <= i; j += 256) {
        float p = __expf(ls[j] - gmax);
        ls[j] = p;
        lsum += p;
    }
#pragma unroll
    for (int o = 16; o; o >>= 1) lsum += __shfl_xor_sync(0xffffffffu, lsum, o);
    if (lane == 0) rbuf[w] = lsum;
    __syncthreads();
    float tot = rbuf[0];
#pragma unroll
    for (int zz = 1; zz < 8; zz++) tot += rbuf[zz];
    const float inv = 1.f / tot;
    __syncthreads();

    // ---- winner: wei@v, vectorized float4 ----
    {
        const int hg = tid & 15;
        const int js = tid >> 4;
        const float4* v4 = (const float4*)(g_v + (size_t)b * TT * 64);
        float4 a4 = make_float4(0.f, 0.f, 0.f, 0.f);
#pragma unroll 4
        for (int j = js; j <= i; j += 16) {
            float wei = ls[j];
            float4 vv = v4[j * 16 + hg];
            a4.x = fmaf(wei, vv.x, a4.x);
            a4.y = fmaf(wei, vv.y, a4.y);
            a4.z = fmaf(wei, vv.z, a4.z);
            a4.w = fmaf(wei, vv.w, a4.w);
        }
        *(float4*)(red + js * 64 + hg * 4) = a4;
        __syncthreads();
        if (tid < 64) {
            float r = 0.f;
#pragma unroll
            for (int s = 0; s < 16; s++) r += red[s * 64 + tid];
            out[bi * 64 + tid] = r * inv;
        }
    }
}

// ---------------- launcher ----------------
extern "C" void kernel_launch(void* const* d_in, const int* in_sizes, int n_in,
                              void* d_out, int out_size)
{
    const float* x     = (const float*)d_in[0];
    const float* pos   = (const float*)d_in[1];
    const float* pdist = (const float*)d_in[2];
    const float* W1    = (const float*)d_in[3];
    const float* b1    = (const float*)d_in[4];
    const float* W2    = (const float*)d_in[5];
    const float* b2    = (const float*)d_in[6];
    const float* Wv    = (const float*)d_in[7];
    const float* bv    = (const float*)d_in[8];
    float* out = (float*)d_out;

    prep_kernel<<<520, 384>>>(x, pos, W1, b1, Wv, bv);
    attn_kernel<<<2 * NCHUNK_BLKS, 256>>>(pdist, W2, b2, out);
}

// round 17
// speedup vs baseline: 1.3867x; 1.0266x over previous
#include <cuda_runtime.h>
#include <cuda_bf16.h>
#include <cstdint>

#define TT 512
#define CC 64
#define NB 1024   // B*T
#define NCHUNK_BLKS 1280

// scratch (allocation-free rule: __device__ globals)
__device__ float g_kp[NB * CC];
__device__ float g_qp[NB * CC];           // qp + b1 folded
__device__ float g_v [NB * CC];
__device__ float g_logits[NB * TT];
__device__ uint4 g_Wfrag[1024];           // B fragments: [kt][nt2][lane]
__device__ int g_cnt[NB];                 // per-row chunk counters (self-reset)

// ---------------- kernel 1: projections (1 token/block) + W1p fragments ----------------
__global__ __launch_bounds__(192) void prep_kernel(
    const float* __restrict__ x, const float* __restrict__ pos,
    const float* __restrict__ W1, const float* __restrict__ b1,
    const float* __restrict__ Wv, const float* __restrict__ bv)
{
    const int tid = threadIdx.x;
    const int bid = blockIdx.x;

    if (bid >= NB) {
        // build B fragments exactly as ldmatrix.x4 would deliver them (proven R11/R12).
        if (tid < 128) {
            int idx  = (bid - NB) * 128 + tid;    // 0..1023
            int lane = idx & 31;
            int nt2  = (idx >> 5) & 3;
            int kt   = idx >> 7;
            int n0 = nt2 * 16 + (lane >> 2);
            int k0 = kt * 16 + 2 * (lane & 3);
            const float* Wp = W1 + 128 * 64;      // W1p base, [k][n]
            float a00 = Wp[(k0    ) * 64 + n0],     a01 = Wp[(k0 + 1) * 64 + n0];
            float a10 = Wp[(k0 + 8) * 64 + n0],     a11 = Wp[(k0 + 9) * 64 + n0];
            float a20 = Wp[(k0    ) * 64 + n0 + 8], a21 = Wp[(k0 + 1) * 64 + n0 + 8];
            float a30 = Wp[(k0 + 8) * 64 + n0 + 8], a31 = Wp[(k0 + 9) * 64 + n0 + 8];
            __nv_bfloat162 h0 = __floats2bfloat162_rn(a00, a01);
            __nv_bfloat162 h1 = __floats2bfloat162_rn(a10, a11);
            __nv_bfloat162 h2 = __floats2bfloat162_rn(a20, a21);
            __nv_bfloat162 h3 = __floats2bfloat162_rn(a30, a31);
            uint4 u;
            u.x = *(uint32_t*)&h0;
            u.y = *(uint32_t*)&h1;
            u.z = *(uint32_t*)&h2;
            u.w = *(uint32_t*)&h3;
            g_Wfrag[idx] = u;
        }
        return;
    }

    __shared__ float xs[64], x1s[64];
    const int bi = bid;                   // token index (b*T + t)
    if (tid < 64) {
        float xv = x[bi * 64 + tid];
        xs [tid] = xv;
        x1s[tid] = xv + pos[(bi & (TT - 1)) * 64 + tid];
    }
    __syncthreads();

    const int m = tid >> 6;               // 0 kp, 1 qp, 2 v
    const int c = tid & 63;

    const float* Wp = (m == 0) ? W1 : (m == 1) ? (W1 + 4096) : Wv;
    const float* in = (m == 2) ? xs : x1s;

    float a = 0.f;
#pragma unroll 16
    for (int k = 0; k < 64; k++)
        a = fmaf(in[k], Wp[k * 64 + c], a);

    if (m == 0)      g_kp[bi * 64 + c] = a;
    else if (m == 1) g_qp[bi * 64 + c] = a + b1[c];
    else             g_v [bi * 64 + c] = a + bv[c];
}

// ---------------- kernel 2: champion attn (R12/R16, unchanged) ----------------
__global__ __launch_bounds__(256, 4) void attn_kernel(
    const float* __restrict__ pdist,
    const float* __restrict__ W2,
    const float* __restrict__ b2,
    float* __restrict__ out)
{
    __shared__ __nv_bfloat16 As[128 * 136];   // 34816 B, padded stride 136
    __shared__ float qp_s[64];
    __shared__ float W2_s[64];                // pre-scaled by 0.125

    // winner aliases over As (dead after MMA phase)
    float* ls    = (float*)As;                // 512 f
    float* red   = (float*)As + 512;          // 16*64 f
    float* rbuf  = (float*)As + 512 + 1024;   // 8 f
    int*   sflag = (int*)((float*)As + 512 + 1024 + 8);

    const int tid = threadIdx.x;

    // decode (b, i, ch)
    int z = blockIdx.x;
    int b = 0;
    if (z >= NCHUNK_BLKS) { b = 1; z -= NCHUNK_BLKS; }
    int ch, i;
    if (z < 512)       { ch = 0; i = z; }
    else if (z < 896)  { ch = 1; i = 128 + (z - 512); }
    else if (z < 1152) { ch = 2; i = 256 + (z - 896); }
    else               { ch = 3; i = 384 + (z - 1152); }
    const int bi    = b * TT + i;
    const int jbase = ch << 7;
    const int imax  = i - jbase;
    const int nch   = (i >> 7) + 1;

    const int lane = tid & 31;
    const int w    = tid >> 5;
    const int g    = lane >> 2;
    const int tc   = lane & 3;
    const int wrow = w * 16;
    const bool active = (wrow <= imax);

    // ---- pdist loads first: DRAM latency up front, per-warp rows ----
    if (active) {
        const int rmaxi = imax - wrow;
        const float4* src = (const float4*)(pdist + ((size_t)bi * TT + jbase) * 128);
#pragma unroll
        for (int r = 0; r < 16; r++) {
            if (r <= rmaxi) {
                int jloc = wrow + r;
                float4 vv = src[jloc * 32 + lane];
                __nv_bfloat162 lo = __floats2bfloat162_rn(vv.x, vv.y);
                __nv_bfloat162 hi = __floats2bfloat162_rn(vv.z, vv.w);
                uint2 u;
                u.x = *(uint32_t*)&lo;
                u.y = *(uint32_t*)&hi;
                *(uint2*)((char*)As + jloc * 272 + lane * 8) = u;
            }
        }
    }
    if (tid < 64) {
        qp_s[tid] = g_qp[bi * 64 + tid];
        W2_s[tid] = W2[tid] * 0.125f;
    }
    __syncthreads();

    if (active) {
        uint32_t As_u = (uint32_t)__cvta_generic_to_shared(As);
        uint32_t a_base = As_u + (uint32_t)((wrow + (lane & 7) + ((lane >> 3) & 1) * 8) * 272
                                            + (lane >> 4) * 16);

        float acc[32];
#pragma unroll
        for (int zz = 0; zz < 32; zz++) acc[zz] = 0.f;

        const uint4* wf = g_Wfrag + lane;

#pragma unroll
        for (int kt = 0; kt < 8; kt++) {
            uint32_t a0, a1, a2, a3;
            asm volatile("ldmatrix.sync.aligned.m8n8.x4.shared.b16 {%0,%1,%2,%3}, [%4];"
                         : "=r"(a0), "=r"(a1), "=r"(a2), "=r"(a3)
                         : "r"(a_base + kt * 32));
#pragma unroll
            for (int nt2 = 0; nt2 < 4; nt2++) {
                uint4 bb = __ldg(wf + (kt * 4 + nt2) * 32);
                asm volatile(
                    "mma.sync.aligned.m16n8k16.row.col.f32.bf16.bf16.f32 "
                    "{%0,%1,%2,%3}, {%4,%5,%6,%7}, {%8,%9}, {%0,%1,%2,%3};"
                    : "+f"(acc[nt2 * 8 + 0]), "+f"(acc[nt2 * 8 + 1]),
                      "+f"(acc[nt2 * 8 + 2]), "+f"(acc[nt2 * 8 + 3])
                    : "r"(a0), "r"(a1), "r"(a2), "r"(a3), "r"(bb.x), "r"(bb.y));
                asm volatile(
                    "mma.sync.aligned.m16n8k16.row.col.f32.bf16.bf16.f32 "
                    "{%0,%1,%2,%3}, {%4,%5,%6,%7}, {%8,%9}, {%0,%1,%2,%3};"
                    : "+f"(acc[nt2 * 8 + 4]), "+f"(acc[nt2 * 8 + 5]),
                      "+f"(acc[nt2 * 8 + 6]), "+f"(acc[nt2 * 8 + 7])
                    : "r"(a0), "r"(a1), "r"(a2), "r"(a3), "r"(bb.z), "r"(bb.w));
            }
        }

        // fused epilogue: +qp_s+kp, gelu (ex2+rcp), dot with pre-scaled W2
        const int j0 = jbase + wrow + g;
        const int j1 = j0 + 8;
        const float* kp0 = g_kp + ((size_t)(b * TT + j0)) * 64;
        const float* kp1 = kp0 + 8 * 64;
        float pa = 0.f, pb = 0.f;
#pragma unroll
        for (int nt = 0; nt < 8; nt++) {
            int c = nt * 8 + 2 * tc;
            float2 k0 = *(const float2*)(kp0 + c);
            float2 k1 = *(const float2*)(kp1 + c);
            float2 qv = *(const float2*)(qp_s + c);
            float w20 = W2_s[c], w21 = W2_s[c + 1];
            float hh, h2, e, d, rc;
            hh = acc[nt * 4 + 0] + qv.x + k0.x;
            h2 = hh * hh;
            asm("ex2.approx.f32 %0, %1;" : "=f"(e)
                : "f"(hh * fmaf(-0.10294324f, h2, -2.3022087f)));
            d = e + 1.f;
            asm("rcp.approx.f32 %0, %1;" : "=f"(rc) : "f"(d));
            pa = fmaf(w20, hh * rc, pa);
            hh = acc[nt * 4 + 1] + qv.y + k0.y;
            h2 = hh * hh;
            asm("ex2.approx.f32 %0, %1;" : "=f"(e)
                : "f"(hh * fmaf(-0.10294324f, h2, -2.3022087f)));
            d = e + 1.f;
            asm("rcp.approx.f32 %0, %1;" : "=f"(rc) : "f"(d));
            pa = fmaf(w21, hh * rc, pa);
            hh = acc[nt * 4 + 2] + qv.x + k1.x;
            h2 = hh * hh;
            asm("ex2.approx.f32 %0, %1;" : "=f"(e)
                : "f"(hh * fmaf(-0.10294324f, h2, -2.3022087f)));
            d = e + 1.f;
            asm("rcp.approx.f32 %0, %1;" : "=f"(rc) : "f"(d));
            pb = fmaf(w20, hh * rc, pb);
            hh = acc[nt * 4 + 3] + qv.y + k1.y;
            h2 = hh * hh;
            asm("ex2.approx.f32 %0, %1;" : "=f"(e)
                : "f"(hh * fmaf(-0.10294324f, h2, -2.3022087f)));
            d = e + 1.f;
            asm("rcp.approx.f32 %0, %1;" : "=f"(rc) : "f"(d));
            pb = fmaf(w21, hh * rc, pb);
        }
        pa += __shfl_xor_sync(0xffffffffu, pa, 1);
        pa += __shfl_xor_sync(0xffffffffu, pa, 2);
        pb += __shfl_xor_sync(0xffffffffu, pb, 1);
        pb += __shfl_xor_sync(0xffffffffu, pb, 2);
        if (tc == 0) {
            g_logits[bi * TT + j0] = pa;   // already ×0.125
            g_logits[bi * TT + j1] = pb;
        }
    }

    // ---- winner election ----
    __syncthreads();
    if (tid == 0) {
        __threadfence();
        int old = atomicAdd(&g_cnt[bi], 1);
        if (old == nch - 1) {
            *sflag = 1;
            g_cnt[bi] = 0;   // self-reset for graph replay
        } else {
            *sflag = 0;
        }
    }
    __syncthreads();
    if (!*sflag) return;
    __threadfence();  // acquire

    // ---- winner: softmax (logits pre-scaled; add b2*0.125) ----
    const float b2v = b2[0] * 0.125f;
    float lmax = -1e30f;
    for (int j = tid; j <= i; j += 256) {
        float l = __ldcg(&g_logits[bi * TT + j]) + b2v;
        ls[j] = l;
        lmax = fmaxf(lmax, l);
    }
#pragma unroll
    for (int o = 16; o; o >>= 1) lmax = fmaxf(lmax, __shfl_xor_sync(0xffffffffu, lmax, o));
    if (lane == 0) rbuf[w] = lmax;
    __syncthreads();
    float gmax = rbuf[0];
#pragma unroll
    for (int zz = 1; zz < 8; zz++) gmax = fmaxf(gmax, rbuf[zz]);
    __syncthreads();

    float lsum = 0.f;
    for (int j = tid; j <= i; j += 256) {
        float p = __expf(ls[j] - gmax);
        ls[j] = p;
        lsum += p;
    }
#pragma unroll
    for (int o = 16; o; o >>= 1) lsum += __shfl_xor_sync(0xffffffffu, lsum, o);
    if (lane == 0) rbuf[w] = lsum;
    __syncthreads();
    float tot = rbuf[0];
#pragma unroll
    for (int zz = 1; zz < 8; zz++) tot += rbuf[zz];
    const float inv = 1.f / tot;
    __syncthreads();

    // ---- winner: wei@v, vectorized float4 ----
    {
        const int hg = tid & 15;
        const int js = tid >> 4;
        const float4* v4 = (const float4*)(g_v + (size_t)b * TT * 64);
        float4 a4 = make_float4(0.f, 0.f, 0.f, 0.f);
#pragma unroll 4
        for (int j = js; j <= i; j += 16) {
            float wei = ls[j];
            float4 vv = v4[j * 16 + hg];
            a4.x = fmaf(wei, vv.x, a4.x);
            a4.y = fmaf(wei, vv.y, a4.y);
            a4.z = fmaf(wei, vv.z, a4.z);
            a4.w = fmaf(wei, vv.w, a4.w);
        }
        *(float4*)(red + js * 64 + hg * 4) = a4;
        __syncthreads();
        if (tid < 64) {
            float r = 0.f;
#pragma unroll
            for (int s = 0; s < 16; s++) r += red[s * 64 + tid];
            out[bi * 64 + tid] = r * inv;
        }
    }
}

// ---------------- launcher ----------------
extern "C" void kernel_launch(void* const* d_in, const int* in_sizes, int n_in,
                              void* d_out, int out_size)
{
    const float* x     = (const float*)d_in[0];
    const float* pos   = (const float*)d_in[1];
    const float* pdist = (const float*)d_in[2];
    const float* W1    = (const float*)d_in[3];
    const float* b1    = (const float*)d_in[4];
    const float* W2    = (const float*)d_in[5];
    const float* b2    = (const float*)d_in[6];
    const float* Wv    = (const float*)d_in[7];
    const float* bv    = (const float*)d_in[8];
    float* out = (float*)d_out;

    prep_kernel<<<NB + 8, 192>>>(x, pos, W1, b1, Wv, bv);
    attn_kernel<<<2 * NCHUNK_BLKS, 256>>>(pdist, W2, b2, out);
}